// round 1
// baseline (speedup 1.0000x reference)
#include <cuda_runtime.h>
#include <math.h>

#define BB 64
#define TT 2048
#define DD 256
#define MM 20
#define TOPK_N 100

// ---------- scratch (no allocations allowed) ----------
__device__ float g_center_pred[BB * TT];
__device__ float g_window_pred[BB * TT];
__device__ float g_offset_pred[BB * TT];
__device__ float g_center_tgt[BB * TT];
__device__ float g_window_tgt[BB * TT];
__device__ float g_offset_tgt[BB * TT];
__device__ float g_weight[BB * TT];
__device__ float g_acc[4];  // 0: center_sum, 1: window_sum, 2: offset_sum, 3: avg_factor

__global__ void init_kernel() {
    if (threadIdx.x < 4) g_acc[threadIdx.x] = 0.0f;
}

// ---------- fused 3-way GEMV + sigmoid + mask ----------
// warp per row; 256 floats/row -> 2 float4 per lane; weights in SMEM
__global__ void proj_kernel(const float* __restrict__ x,
                            const float* __restrict__ wc, const float* __restrict__ bc,
                            const float* __restrict__ ww, const float* __restrict__ bw,
                            const float* __restrict__ wo, const float* __restrict__ bo,
                            const float* __restrict__ sal) {
    __shared__ float s_wc[DD], s_ww[DD], s_wo[DD];
    int tid = threadIdx.x;
    for (int i = tid; i < DD; i += blockDim.x) {
        s_wc[i] = wc[i]; s_ww[i] = ww[i]; s_wo[i] = wo[i];
    }
    __syncthreads();

    int warp = tid >> 5, lane = tid & 31;
    int row = blockIdx.x * 8 + warp;   // grid sized exactly: B*T/8 blocks
    const float4* xr = reinterpret_cast<const float4*>(x + (size_t)row * DD);
    const float4* w0 = reinterpret_cast<const float4*>(s_wc);
    const float4* w1 = reinterpret_cast<const float4*>(s_ww);
    const float4* w2 = reinterpret_cast<const float4*>(s_wo);

    float sc = 0.f, sw = 0.f, so = 0.f;
#pragma unroll
    for (int c = 0; c < 2; c++) {
        int j = lane + 32 * c;
        float4 v = xr[j];
        float4 a = w0[j];
        sc += v.x * a.x + v.y * a.y + v.z * a.z + v.w * a.w;
        float4 b = w1[j];
        sw += v.x * b.x + v.y * b.y + v.z * b.z + v.w * b.w;
        float4 d = w2[j];
        so += v.x * d.x + v.y * d.y + v.z * d.z + v.w * d.w;
    }
#pragma unroll
    for (int o = 16; o; o >>= 1) {
        sc += __shfl_xor_sync(0xffffffffu, sc, o);
        sw += __shfl_xor_sync(0xffffffffu, sw, o);
        so += __shfl_xor_sync(0xffffffffu, so, o);
    }
    if (lane == 0) {
        float mask = (sal[row] >= 0.f) ? 1.f : 0.f;
        float z = sc + bc[0];
        g_center_pred[row] = (1.f / (1.f + expf(-z))) * mask;
        g_window_pred[row] = sw + bw[0];
        g_offset_pred[row] = so + bo[0];
    }
}

// ---------- targets ----------
__global__ void targets_kernel(const float* __restrict__ boundary) {
    __shared__ int   s_valid[MM];
    __shared__ int   s_ci[MM];
    __shared__ int   s_rad[MM];
    __shared__ float s_inv[MM];      // 1/(2*sigma^2)
    __shared__ float s_win[MM];
    __shared__ float s_cfrac[MM];    // centers - ci

    int b = blockIdx.x, tid = threadIdx.x;
    if (tid < MM) {
        float b0 = boundary[(b * MM + tid) * 2 + 0];
        float b1 = boundary[(b * MM + tid) * 2 + 1];
        int valid = (b0 != -1.0f);
        float b0c = b0 * 0.5f;              // / UNIT (=2)
        float b1c = (b1 - 2.0f) * 0.5f;     // (b1 - UNIT)/UNIT
        float center = fminf((b0c + b1c) * 0.5f, (float)TT - 0.5f);
        float window = b1c - b0c;
        int radius = (int)(window * 0.2f);  // trunc like .astype(int32)
        float sigma = ((float)radius + 1.0f) * 0.2f;
        int ci = (int)center;               // center >= 0 when valid
        s_valid[tid] = valid;
        s_ci[tid]    = ci;
        s_rad[tid]   = radius;
        s_inv[tid]   = 1.0f / (2.0f * sigma * sigma);
        s_win[tid]   = window;
        s_cfrac[tid] = center - (float)ci;
    }
    __syncthreads();

    for (int t = tid; t < TT; t += blockDim.x) {
        float m = 0.f;
#pragma unroll
        for (int j = 0; j < MM; j++) {
            if (!s_valid[j]) continue;
            int d = t - s_ci[j];
            if (abs(d) <= s_rad[j]) {
                float g = expf(-(float)(d * d) * s_inv[j]);
                m = fmaxf(m, g);
            }
        }
        int idx = b * TT + t;
        g_center_tgt[idx] = m;
        g_window_tgt[idx] = 0.f;
        g_offset_tgt[idx] = 0.f;
        g_weight[idx]     = 0.f;
    }
    __syncthreads();

    if (tid == 0) {
        int cnt = 0;
        for (int j = 0; j < MM; j++) {       // sequential: last write wins (duplicate ci)
            if (!s_valid[j]) continue;
            cnt++;
            int idx = b * TT + s_ci[j];
            g_window_tgt[idx] = s_win[j];
            g_offset_tgt[idx] = s_cfrac[j];
            g_weight[idx]     = 1.0f;
        }
        atomicAdd(&g_acc[3], (float)cnt);
    }
}

// ---------- loss reduction ----------
__global__ void loss_kernel(const float* __restrict__ sal) {
    float cs = 0.f, ws = 0.f, os = 0.f;
    int stride = gridDim.x * blockDim.x;
    for (int i = blockIdx.x * blockDim.x + threadIdx.x; i < BB * TT; i += stride) {
        float mask = (sal[i] >= 0.f) ? 1.f : 0.f;
        float cp = g_center_pred[i];
        float ct = g_center_tgt[i];
        float pos = (ct == 1.0f) ? 1.f : 0.f;
        float omc = 1.f - cp;
        float pl = -logf(cp + 1e-12f) * omc * omc * pos;
        float omt = 1.f - ct;
        float o2 = omt * omt;
        float nl = -logf(omc + 1e-12f) * cp * cp * (o2 * o2);
        cs += (pl + nl) * mask;
        float w = g_weight[i];
        ws += fabsf(g_window_pred[i] - g_window_tgt[i]) * w;
        os += fabsf(g_offset_pred[i] - g_offset_tgt[i]) * w;
    }
#pragma unroll
    for (int o = 16; o; o >>= 1) {
        cs += __shfl_xor_sync(0xffffffffu, cs, o);
        ws += __shfl_xor_sync(0xffffffffu, ws, o);
        os += __shfl_xor_sync(0xffffffffu, os, o);
    }
    __shared__ float r0[8], r1[8], r2[8];
    int lane = threadIdx.x & 31, w = threadIdx.x >> 5;
    if (lane == 0) { r0[w] = cs; r1[w] = ws; r2[w] = os; }
    __syncthreads();
    if (w == 0) {
        cs = (lane < 8) ? r0[lane] : 0.f;
        ws = (lane < 8) ? r1[lane] : 0.f;
        os = (lane < 8) ? r2[lane] : 0.f;
#pragma unroll
        for (int o = 4; o; o >>= 1) {
            cs += __shfl_xor_sync(0xffffffffu, cs, o);
            ws += __shfl_xor_sync(0xffffffffu, ws, o);
            os += __shfl_xor_sync(0xffffffffu, os, o);
        }
        if (lane == 0) {
            atomicAdd(&g_acc[0], cs);
            atomicAdd(&g_acc[1], ws);
            atomicAdd(&g_acc[2], os);
        }
    }
}

// ---------- NMS + top-k + boundary decode ----------
// One block per batch row. Keys = (f32bits(cp) << 32) | (T-1-t):
// descending sort => value desc, tie-break lower index first (matches jax.lax.top_k).
__global__ void boundary_kernel(float* __restrict__ out) {
    __shared__ float s_cp[TT];
    __shared__ unsigned long long s_key[TT];
    int b = blockIdx.x, tid = threadIdx.x;

    for (int t = tid; t < TT; t += blockDim.x) s_cp[t] = g_center_pred[b * TT + t];
    __syncthreads();

    for (int t = tid; t < TT; t += blockDim.x) {
        float c = s_cp[t];
        float l = (t > 0)      ? s_cp[t - 1] : -INFINITY;
        float r = (t < TT - 1) ? s_cp[t + 1] : -INFINITY;
        float hmax = fmaxf(c, fmaxf(l, r));
        float cpv = (hmax == c) ? c : 0.f;             // cpv >= 0 always
        unsigned int bits = __float_as_uint(cpv);
        s_key[t] = ((unsigned long long)bits << 32) | (unsigned int)(TT - 1 - t);
    }
    __syncthreads();

    // bitonic sort, descending
    for (int k = 2; k <= TT; k <<= 1) {
        for (int j = k >> 1; j > 0; j >>= 1) {
            for (int i = tid; i < TT; i += blockDim.x) {
                int ixj = i ^ j;
                if (ixj > i) {
                    bool up = ((i & k) == 0);
                    unsigned long long a = s_key[i], c2 = s_key[ixj];
                    if ((a < c2) == up) { s_key[i] = c2; s_key[ixj] = a; }
                }
            }
            __syncthreads();
        }
    }

    for (int t = tid; t < TOPK_N; t += blockDim.x) {
        unsigned long long key = s_key[t];
        float score = __uint_as_float((unsigned int)(key >> 32));
        int idx = TT - 1 - (int)(key & 0xffffffffu);
        float off = fmaxf(g_offset_pred[b * TT + idx], 0.f);
        float center = (float)idx + off;
        float window = fmaxf(g_window_pred[b * TT + idx], 0.f);
        float lo = fminf(fmaxf(center - window * 0.5f, 0.f), (float)(TT - 1)) * 2.0f;
        float hi = fminf(fmaxf(center + window * 0.5f, 0.f), (float)(TT - 1)) * 2.0f + 2.0f;
        float* o = out + ((size_t)b * TOPK_N + t) * 3;
        o[0] = lo; o[1] = hi; o[2] = score;
    }
}

__global__ void finalize_kernel(float* __restrict__ out) {
    if (threadIdx.x == 0) {
        float avg = g_acc[3];
        out[BB * TOPK_N * 3 + 0] = g_acc[0] / avg;
        out[BB * TOPK_N * 3 + 1] = 0.1f * g_acc[1] / avg;
        out[BB * TOPK_N * 3 + 2] = g_acc[2] / avg;
    }
}

extern "C" void kernel_launch(void* const* d_in, const int* in_sizes, int n_in,
                              void* d_out, int out_size) {
    const float* x        = (const float*)d_in[0];
    const float* w_center = (const float*)d_in[1];
    const float* b_center = (const float*)d_in[2];
    const float* w_window = (const float*)d_in[3];
    const float* b_window = (const float*)d_in[4];
    const float* w_offset = (const float*)d_in[5];
    const float* b_offset = (const float*)d_in[6];
    const float* saliency = (const float*)d_in[7];
    const float* boundary = (const float*)d_in[8];
    float* out = (float*)d_out;

    init_kernel<<<1, 32>>>();
    proj_kernel<<<(BB * TT) / 8, 256>>>(x, w_center, b_center, w_window, b_window,
                                        w_offset, b_offset, saliency);
    targets_kernel<<<BB, 256>>>(boundary);
    loss_kernel<<<256, 256>>>(saliency);
    boundary_kernel<<<BB, 512>>>(out);
    finalize_kernel<<<1, 32>>>(out);
}

// round 2
// speedup vs baseline: 1.0213x; 1.0213x over previous
#include <cuda_runtime.h>
#include <math.h>

#define BB 64
#define TT 2048
#define DD 256
#define MM 20
#define TOPK_N 100

// ---------- scratch (no allocations allowed) ----------
__device__ float g_center_pred[BB * TT];
__device__ float g_window_pred[BB * TT];
__device__ float g_offset_pred[BB * TT];
__device__ float g_acc[4];  // 0: center_sum, 1: window_sum, 2: offset_sum, 3: avg_factor

// ---------- fused 3-way GEMV + sigmoid + mask (+ g_acc zeroing) ----------
// warp per row; 256 floats/row -> 2 float4 per lane; weights in SMEM
__global__ void proj_kernel(const float* __restrict__ x,
                            const float* __restrict__ wc, const float* __restrict__ bc,
                            const float* __restrict__ ww, const float* __restrict__ bw,
                            const float* __restrict__ wo, const float* __restrict__ bo,
                            const float* __restrict__ sal) {
    __shared__ float s_wc[DD], s_ww[DD], s_wo[DD];
    int tid = threadIdx.x;
    if (blockIdx.x == 0 && tid < 4) g_acc[tid] = 0.0f;   // replaces init_kernel
    for (int i = tid; i < DD; i += blockDim.x) {
        s_wc[i] = wc[i]; s_ww[i] = ww[i]; s_wo[i] = wo[i];
    }
    __syncthreads();

    int warp = tid >> 5, lane = tid & 31;
    int row = blockIdx.x * 8 + warp;   // grid sized exactly: B*T/8 blocks
    const float4* xr = reinterpret_cast<const float4*>(x + (size_t)row * DD);
    const float4* w0 = reinterpret_cast<const float4*>(s_wc);
    const float4* w1 = reinterpret_cast<const float4*>(s_ww);
    const float4* w2 = reinterpret_cast<const float4*>(s_wo);

    float sc = 0.f, sw = 0.f, so = 0.f;
#pragma unroll
    for (int c = 0; c < 2; c++) {
        int j = lane + 32 * c;
        float4 v = xr[j];
        float4 a = w0[j];
        sc += v.x * a.x + v.y * a.y + v.z * a.z + v.w * a.w;
        float4 b = w1[j];
        sw += v.x * b.x + v.y * b.y + v.z * b.z + v.w * b.w;
        float4 d = w2[j];
        so += v.x * d.x + v.y * d.y + v.z * d.z + v.w * d.w;
    }
#pragma unroll
    for (int o = 16; o; o >>= 1) {
        sc += __shfl_xor_sync(0xffffffffu, sc, o);
        sw += __shfl_xor_sync(0xffffffffu, sw, o);
        so += __shfl_xor_sync(0xffffffffu, so, o);
    }
    if (lane == 0) {
        float mask = (sal[row] >= 0.f) ? 1.f : 0.f;
        float z = sc + bc[0];
        g_center_pred[row] = (1.f / (1.f + expf(-z))) * mask;
        g_window_pred[row] = sw + bw[0];
        g_offset_pred[row] = so + bo[0];
    }
}

// ---------- fused targets + loss ----------
// One block per batch. Computes center_tgt / scatter targets on the fly and
// accumulates the three loss sums + avg_factor directly (no [B,T] tgt arrays).
__global__ void targets_loss_kernel(const float* __restrict__ boundary,
                                    const float* __restrict__ sal) {
    __shared__ int   s_valid[MM];
    __shared__ int   s_ci[MM];
    __shared__ int   s_rad[MM];
    __shared__ float s_inv[MM];      // 1/(2*sigma^2)
    __shared__ float s_win[MM];
    __shared__ float s_cfrac[MM];    // centers - ci

    int b = blockIdx.x, tid = threadIdx.x;
    if (tid < MM) {
        float b0 = boundary[(b * MM + tid) * 2 + 0];
        float b1 = boundary[(b * MM + tid) * 2 + 1];
        int valid = (b0 != -1.0f);
        float b0c = b0 * 0.5f;              // / UNIT (=2)
        float b1c = (b1 - 2.0f) * 0.5f;     // (b1 - UNIT)/UNIT
        float center = fminf((b0c + b1c) * 0.5f, (float)TT - 0.5f);
        float window = b1c - b0c;
        int radius = (int)(window * 0.2f);  // trunc like .astype(int32)
        float sigma = ((float)radius + 1.0f) * 0.2f;
        int ci = (int)center;               // center >= 0 when valid
        s_valid[tid] = valid;
        s_ci[tid]    = ci;
        s_rad[tid]   = radius;
        s_inv[tid]   = 1.0f / (2.0f * sigma * sigma);
        s_win[tid]   = window;
        s_cfrac[tid] = center - (float)ci;
    }
    __syncthreads();

    float cs = 0.f, ws = 0.f, os = 0.f;
    for (int t = tid; t < TT; t += blockDim.x) {
        // center target = scatter-max of truncated gaussians
        float ct = 0.f;
        // window/offset/weight scatter: last valid j with ci==t wins
        int last = -1;
#pragma unroll
        for (int j = 0; j < MM; j++) {
            if (!s_valid[j]) continue;
            int d = t - s_ci[j];
            if (abs(d) <= s_rad[j]) {
                float g = expf(-(float)(d * d) * s_inv[j]);
                ct = fmaxf(ct, g);
            }
            if (d == 0) last = j;
        }
        int idx = b * TT + t;
        float mask = (sal[idx] >= 0.f) ? 1.f : 0.f;
        float cp = g_center_pred[idx];
        float pos = (ct == 1.0f) ? 1.f : 0.f;
        float omc = 1.f - cp;
        float pl = -logf(cp + 1e-12f) * omc * omc * pos;
        float omt = 1.f - ct;
        float o2 = omt * omt;
        float nl = -logf(omc + 1e-12f) * cp * cp * (o2 * o2);
        cs += (pl + nl) * mask;
        if (last >= 0) {
            ws += fabsf(g_window_pred[idx] - s_win[last]);
            os += fabsf(g_offset_pred[idx] - s_cfrac[last]);
        }
    }

    // block reduce (256 threads = 8 warps)
#pragma unroll
    for (int o = 16; o; o >>= 1) {
        cs += __shfl_xor_sync(0xffffffffu, cs, o);
        ws += __shfl_xor_sync(0xffffffffu, ws, o);
        os += __shfl_xor_sync(0xffffffffu, os, o);
    }
    __shared__ float r0[8], r1[8], r2[8];
    int lane = tid & 31, w = tid >> 5;
    if (lane == 0) { r0[w] = cs; r1[w] = ws; r2[w] = os; }
    __syncthreads();
    if (w == 0) {
        cs = (lane < 8) ? r0[lane] : 0.f;
        ws = (lane < 8) ? r1[lane] : 0.f;
        os = (lane < 8) ? r2[lane] : 0.f;
#pragma unroll
        for (int o = 4; o; o >>= 1) {
            cs += __shfl_xor_sync(0xffffffffu, cs, o);
            ws += __shfl_xor_sync(0xffffffffu, ws, o);
            os += __shfl_xor_sync(0xffffffffu, os, o);
        }
        if (lane == 0) {
            atomicAdd(&g_acc[0], cs);
            atomicAdd(&g_acc[1], ws);
            atomicAdd(&g_acc[2], os);
        }
    }
    if (tid == 0) {
        int cnt = 0;
#pragma unroll
        for (int j = 0; j < MM; j++) cnt += s_valid[j];
        atomicAdd(&g_acc[3], (float)cnt);
    }
}

// ---------- NMS + top-k + boundary decode ----------
// One block per batch row, 1024 threads (2 elements each in the sort).
// Keys = (f32bits(cp) << 32) | (T-1-t): descending sort => value desc,
// tie-break lower index first (matches jax.lax.top_k).
__global__ void boundary_kernel(float* __restrict__ out) {
    __shared__ float s_cp[TT];
    __shared__ unsigned long long s_key[TT];
    int b = blockIdx.x, tid = threadIdx.x;

    for (int t = tid; t < TT; t += blockDim.x) s_cp[t] = g_center_pred[b * TT + t];
    __syncthreads();

    for (int t = tid; t < TT; t += blockDim.x) {
        float c = s_cp[t];
        float l = (t > 0)      ? s_cp[t - 1] : -INFINITY;
        float r = (t < TT - 1) ? s_cp[t + 1] : -INFINITY;
        float hmax = fmaxf(c, fmaxf(l, r));
        float cpv = (hmax == c) ? c : 0.f;             // cpv >= 0 always
        unsigned int bits = __float_as_uint(cpv);
        s_key[t] = ((unsigned long long)bits << 32) | (unsigned int)(TT - 1 - t);
    }
    __syncthreads();

    // bitonic sort, descending; 1024 threads -> 2 compare slots each
    for (int k = 2; k <= TT; k <<= 1) {
        for (int j = k >> 1; j > 0; j >>= 1) {
#pragma unroll
            for (int r = 0; r < 2; r++) {
                int i = tid + r * 1024;
                int ixj = i ^ j;
                if (ixj > i) {
                    bool up = ((i & k) == 0);
                    unsigned long long a = s_key[i], c2 = s_key[ixj];
                    if ((a < c2) == up) { s_key[i] = c2; s_key[ixj] = a; }
                }
            }
            __syncthreads();
        }
    }

    if (tid < TOPK_N) {
        unsigned long long key = s_key[tid];
        float score = __uint_as_float((unsigned int)(key >> 32));
        int idx = TT - 1 - (int)(key & 0xffffffffu);
        float off = fmaxf(g_offset_pred[b * TT + idx], 0.f);
        float center = (float)idx + off;
        float window = fmaxf(g_window_pred[b * TT + idx], 0.f);
        float lo = fminf(fmaxf(center - window * 0.5f, 0.f), (float)(TT - 1)) * 2.0f;
        float hi = fminf(fmaxf(center + window * 0.5f, 0.f), (float)(TT - 1)) * 2.0f + 2.0f;
        float* o = out + ((size_t)b * TOPK_N + tid) * 3;
        o[0] = lo; o[1] = hi; o[2] = score;
    }
}

__global__ void finalize_kernel(float* __restrict__ out) {
    if (threadIdx.x == 0) {
        float avg = g_acc[3];
        out[BB * TOPK_N * 3 + 0] = g_acc[0] / avg;
        out[BB * TOPK_N * 3 + 1] = 0.1f * g_acc[1] / avg;
        out[BB * TOPK_N * 3 + 2] = g_acc[2] / avg;
    }
}

extern "C" void kernel_launch(void* const* d_in, const int* in_sizes, int n_in,
                              void* d_out, int out_size) {
    const float* x        = (const float*)d_in[0];
    const float* w_center = (const float*)d_in[1];
    const float* b_center = (const float*)d_in[2];
    const float* w_window = (const float*)d_in[3];
    const float* b_window = (const float*)d_in[4];
    const float* w_offset = (const float*)d_in[5];
    const float* b_offset = (const float*)d_in[6];
    const float* saliency = (const float*)d_in[7];
    const float* boundary = (const float*)d_in[8];
    float* out = (float*)d_out;

    proj_kernel<<<(BB * TT) / 8, 256>>>(x, w_center, b_center, w_window, b_window,
                                        w_offset, b_offset, saliency);
    targets_loss_kernel<<<BB, 256>>>(boundary, saliency);
    boundary_kernel<<<BB, 1024>>>(out);
    finalize_kernel<<<1, 32>>>(out);
}

// round 4
// speedup vs baseline: 1.3009x; 1.2738x over previous
#include <cuda_runtime.h>
#include <math.h>

#define BB 64
#define TT 2048
#define DD 256
#define MM 20
#define TOPK_N 100

typedef unsigned long long u64;

// ---------- scratch (no allocations allowed) ----------
__device__ float g_center_pred[BB * TT];
__device__ float g_window_pred[BB * TT];
__device__ float g_offset_pred[BB * TT];
__device__ float g_acc[4];   // 0: center_sum, 1: window_sum, 2: offset_sum, 3: avg_factor
__device__ unsigned int g_ticket;

// ---------- fused 3-way GEMV + sigmoid + mask (+ g_acc zeroing) ----------
__global__ void proj_kernel(const float* __restrict__ x,
                            const float* __restrict__ wc, const float* __restrict__ bc,
                            const float* __restrict__ ww, const float* __restrict__ bw,
                            const float* __restrict__ wo, const float* __restrict__ bo,
                            const float* __restrict__ sal) {
    __shared__ float s_wc[DD], s_ww[DD], s_wo[DD];
    int tid = threadIdx.x;
    if (blockIdx.x == 0 && tid < 4) g_acc[tid] = 0.0f;
    for (int i = tid; i < DD; i += blockDim.x) {
        s_wc[i] = wc[i]; s_ww[i] = ww[i]; s_wo[i] = wo[i];
    }
    __syncthreads();

    int warp = tid >> 5, lane = tid & 31;
    int row = blockIdx.x * 8 + warp;   // grid = B*T/8 blocks exactly
    const float4* xr = reinterpret_cast<const float4*>(x + (size_t)row * DD);
    const float4* w0 = reinterpret_cast<const float4*>(s_wc);
    const float4* w1 = reinterpret_cast<const float4*>(s_ww);
    const float4* w2 = reinterpret_cast<const float4*>(s_wo);

    float sc = 0.f, sw = 0.f, so = 0.f;
#pragma unroll
    for (int c = 0; c < 2; c++) {
        int j = lane + 32 * c;
        float4 v = xr[j];
        float4 a = w0[j];
        sc += v.x * a.x + v.y * a.y + v.z * a.z + v.w * a.w;
        float4 b = w1[j];
        sw += v.x * b.x + v.y * b.y + v.z * b.z + v.w * b.w;
        float4 d = w2[j];
        so += v.x * d.x + v.y * d.y + v.z * d.z + v.w * d.w;
    }
#pragma unroll
    for (int o = 16; o; o >>= 1) {
        sc += __shfl_xor_sync(0xffffffffu, sc, o);
        sw += __shfl_xor_sync(0xffffffffu, sw, o);
        so += __shfl_xor_sync(0xffffffffu, so, o);
    }
    if (lane == 0) {
        float mask = (sal[row] >= 0.f) ? 1.f : 0.f;
        float z = sc + bc[0];
        g_center_pred[row] = (1.f / (1.f + expf(-z))) * mask;
        g_window_pred[row] = sw + bw[0];
        g_offset_pred[row] = so + bo[0];
    }
}

// bitonic compare-exchange via warp shuffle (j <= 16), descending sort overall
__device__ __forceinline__ u64 bshfl(u64 v, int i, int j, int k) {
    u64 pv = __shfl_xor_sync(0xffffffffu, v, j);
    bool lower = ((i & j) == 0);
    bool up = ((i & k) == 0);
    u64 mx = v > pv ? v : pv;
    u64 mn = v > pv ? pv : v;
    return (lower == up) ? mx : mn;
}

// ---------- fused targets+loss + NMS + top-k + decode + finalize ----------
// One block (1024 thr) per batch row.
__global__ void fused_tail_kernel(const float* __restrict__ boundary,
                                  const float* __restrict__ sal,
                                  float* __restrict__ out) {
    __shared__ float s_cp[TT];
    __shared__ u64   s_key[TT];
    __shared__ int   s_valid[MM];
    __shared__ int   s_ci[MM];
    __shared__ int   s_rad[MM];
    __shared__ float s_inv[MM];
    __shared__ float s_win[MM];
    __shared__ float s_cfrac[MM];
    __shared__ float s_red[96];
    __shared__ int   s_last;

    int b = blockIdx.x, tid = threadIdx.x;

    // object params
    if (tid < MM) {
        float b0 = boundary[(b * MM + tid) * 2 + 0];
        float b1 = boundary[(b * MM + tid) * 2 + 1];
        int valid = (b0 != -1.0f);
        float b0c = b0 * 0.5f;
        float b1c = (b1 - 2.0f) * 0.5f;
        float center = fminf((b0c + b1c) * 0.5f, (float)TT - 0.5f);
        float window = b1c - b0c;
        int radius = (int)(window * 0.2f);
        float sigma = ((float)radius + 1.0f) * 0.2f;
        int ci = (int)center;
        s_valid[tid] = valid;
        s_ci[tid]    = ci;
        s_rad[tid]   = radius;
        s_inv[tid]   = 1.0f / (2.0f * sigma * sigma);
        s_win[tid]   = window;
        s_cfrac[tid] = center - (float)ci;
    }
    // load cp row into smem
    for (int t = tid; t < TT; t += 1024) s_cp[t] = g_center_pred[b * TT + t];
    __syncthreads();

    // ---- targets + loss ----
    float cs = 0.f, ws = 0.f, os = 0.f;
#pragma unroll
    for (int r = 0; r < 2; r++) {
        int t = tid + r * 1024;
        float ct = 0.f;
        int last = -1;
#pragma unroll
        for (int j = 0; j < MM; j++) {
            if (!s_valid[j]) continue;
            int d = t - s_ci[j];
            if (abs(d) <= s_rad[j]) ct = fmaxf(ct, expf(-(float)(d * d) * s_inv[j]));
            if (d == 0) last = j;
        }
        int idx = b * TT + t;
        float mask = (sal[idx] >= 0.f) ? 1.f : 0.f;
        float cp = s_cp[t];
        float pos = (ct == 1.0f) ? 1.f : 0.f;
        float omc = 1.f - cp;
        float pl = -logf(cp + 1e-12f) * omc * omc * pos;
        float omt = 1.f - ct;
        float o2 = omt * omt;
        float nl = -logf(omc + 1e-12f) * cp * cp * (o2 * o2);
        cs += (pl + nl) * mask;
        if (last >= 0) {
            ws += fabsf(g_window_pred[idx] - s_win[last]);
            os += fabsf(g_offset_pred[idx] - s_cfrac[last]);
        }
    }
#pragma unroll
    for (int o = 16; o; o >>= 1) {
        cs += __shfl_xor_sync(0xffffffffu, cs, o);
        ws += __shfl_xor_sync(0xffffffffu, ws, o);
        os += __shfl_xor_sync(0xffffffffu, os, o);
    }
    int lane = tid & 31, w = tid >> 5;
    if (lane == 0) { s_red[w] = cs; s_red[32 + w] = ws; s_red[64 + w] = os; }

    // ---- peak keys straight into registers ----
    // key = (f32bits(cpv) << 32) | (T-1-t) : descending sort -> value desc, index asc
    u64 e0, e1;
#pragma unroll
    for (int r = 0; r < 2; r++) {
        int t = tid + r * 1024;
        float c = s_cp[t];
        float l = (t > 0)      ? s_cp[t - 1] : -INFINITY;
        float rr = (t < TT - 1) ? s_cp[t + 1] : -INFINITY;
        float hmax = fmaxf(c, fmaxf(l, rr));
        float cpv = (hmax == c) ? c : 0.f;
        u64 key = ((u64)__float_as_uint(cpv) << 32) | (unsigned int)(TT - 1 - t);
        if (r == 0) e0 = key; else e1 = key;
    }

    // warp 0 finishes loss reduction while others start the sort (no extra barrier
    // needed before sort: s_key not yet touched; s_red written above)
    __syncthreads();
    if (w == 0) {
        float a = s_red[lane], bb2 = s_red[32 + lane], c = s_red[64 + lane];
#pragma unroll
        for (int o = 16; o; o >>= 1) {
            a += __shfl_xor_sync(0xffffffffu, a, o);
            bb2 += __shfl_xor_sync(0xffffffffu, bb2, o);
            c += __shfl_xor_sync(0xffffffffu, c, o);
        }
        if (lane == 0) {
            atomicAdd(&g_acc[0], a);
            atomicAdd(&g_acc[1], bb2);
            atomicAdd(&g_acc[2], c);
            int cnt = 0;
#pragma unroll
            for (int j = 0; j < MM; j++) cnt += s_valid[j];
            atomicAdd(&g_acc[3], (float)cnt);
        }
    }

    // ---- bitonic sort (descending), hybrid register/SMEM ----
    int i0 = tid, i1 = tid + 1024;
    // k = 2..32: fully intra-warp
#pragma unroll
    for (int k = 2; k <= 32; k <<= 1) {
#pragma unroll
        for (int j = k >> 1; j > 0; j >>= 1) {
            e0 = bshfl(e0, i0, j, k);
            e1 = bshfl(e1, i1, j, k);
        }
    }
    s_key[i0] = e0; s_key[i1] = e1;
    __syncthreads();
    // k = 64..2048
    for (int k = 64; k <= TT; k <<= 1) {
        for (int j = k >> 1; j >= 32; j >>= 1) {
#pragma unroll
            for (int r = 0; r < 2; r++) {
                int i = tid + r * 1024;
                int ixj = i ^ j;
                if (ixj > i) {
                    bool up = ((i & k) == 0);
                    u64 a = s_key[i], c2 = s_key[ixj];
                    if ((a < c2) == up) { s_key[i] = c2; s_key[ixj] = a; }
                }
            }
            __syncthreads();
        }
        // j = 16..1 in registers
        e0 = s_key[i0]; e1 = s_key[i1];
#pragma unroll
        for (int j = 16; j > 0; j >>= 1) {
            e0 = bshfl(e0, i0, j, k);
            e1 = bshfl(e1, i1, j, k);
        }
        s_key[i0] = e0; s_key[i1] = e1;
        __syncthreads();
    }

    // ---- decode top-k ----
    if (tid < TOPK_N) {
        u64 key = s_key[tid];
        float score = __uint_as_float((unsigned int)(key >> 32));
        int idx = TT - 1 - (int)(key & 0xffffffffu);
        float off = fmaxf(g_offset_pred[b * TT + idx], 0.f);
        float center = (float)idx + off;
        float window = fmaxf(g_window_pred[b * TT + idx], 0.f);
        float lo = fminf(fmaxf(center - window * 0.5f, 0.f), (float)(TT - 1)) * 2.0f;
        float hi = fminf(fmaxf(center + window * 0.5f, 0.f), (float)(TT - 1)) * 2.0f + 2.0f;
        float* o = out + ((size_t)b * TOPK_N + tid) * 3;
        o[0] = lo; o[1] = hi; o[2] = score;
    }

    // ---- finalize: last block writes losses ----
    __syncthreads();
    if (tid == 0) {
        __threadfence();
        unsigned int old = atomicAdd(&g_ticket, 1u);
        s_last = (old == BB - 1) ? 1 : 0;
    }
    __syncthreads();
    if (s_last && tid == 0) {
        __threadfence();
        float avg = g_acc[3];
        out[BB * TOPK_N * 3 + 0] = g_acc[0] / avg;
        out[BB * TOPK_N * 3 + 1] = 0.1f * g_acc[1] / avg;
        out[BB * TOPK_N * 3 + 2] = g_acc[2] / avg;
        g_ticket = 0;   // reset for next graph replay
    }
}

extern "C" void kernel_launch(void* const* d_in, const int* in_sizes, int n_in,
                              void* d_out, int out_size) {
    const float* x        = (const float*)d_in[0];
    const float* w_center = (const float*)d_in[1];
    const float* b_center = (const float*)d_in[2];
    const float* w_window = (const float*)d_in[3];
    const float* b_window = (const float*)d_in[4];
    const float* w_offset = (const float*)d_in[5];
    const float* b_offset = (const float*)d_in[6];
    const float* saliency = (const float*)d_in[7];
    const float* boundary = (const float*)d_in[8];
    float* out = (float*)d_out;

    proj_kernel<<<(BB * TT) / 8, 256>>>(x, w_center, b_center, w_window, b_window,
                                        w_offset, b_offset, saliency);
    fused_tail_kernel<<<BB, 1024>>>(boundary, saliency, out);
}

// round 5
// speedup vs baseline: 1.4805x; 1.1380x over previous
#include <cuda_runtime.h>
#include <math.h>

#define BB 64
#define TT 2048
#define DD 256
#define MM 20
#define TOPK_N 100

typedef unsigned long long u64;

// ---------- scratch (no allocations allowed) ----------
__device__ float g_center_pred[BB * TT];
__device__ float g_window_pred[BB * TT];
__device__ float g_offset_pred[BB * TT];
__device__ float g_acc[4];   // 0: center_sum, 1: window_sum, 2: offset_sum, 3: avg_factor
__device__ unsigned int g_ticket;

// ---------- fused 3-way GEMV + sigmoid + mask (+ g_acc zeroing) ----------
__global__ void proj_kernel(const float* __restrict__ x,
                            const float* __restrict__ wc, const float* __restrict__ bc,
                            const float* __restrict__ ww, const float* __restrict__ bw,
                            const float* __restrict__ wo, const float* __restrict__ bo,
                            const float* __restrict__ sal) {
    __shared__ float s_wc[DD], s_ww[DD], s_wo[DD];
    int tid = threadIdx.x;
    if (blockIdx.x == 0 && tid < 4) g_acc[tid] = 0.0f;
    for (int i = tid; i < DD; i += blockDim.x) {
        s_wc[i] = wc[i]; s_ww[i] = ww[i]; s_wo[i] = wo[i];
    }
    __syncthreads();

    int warp = tid >> 5, lane = tid & 31;
    int row = blockIdx.x * 8 + warp;   // grid = B*T/8 blocks exactly
    const float4* xr = reinterpret_cast<const float4*>(x + (size_t)row * DD);
    const float4* w0 = reinterpret_cast<const float4*>(s_wc);
    const float4* w1 = reinterpret_cast<const float4*>(s_ww);
    const float4* w2 = reinterpret_cast<const float4*>(s_wo);

    float sc = 0.f, sw = 0.f, so = 0.f;
#pragma unroll
    for (int c = 0; c < 2; c++) {
        int j = lane + 32 * c;
        float4 v = xr[j];
        float4 a = w0[j];
        sc += v.x * a.x + v.y * a.y + v.z * a.z + v.w * a.w;
        float4 b = w1[j];
        sw += v.x * b.x + v.y * b.y + v.z * b.z + v.w * b.w;
        float4 d = w2[j];
        so += v.x * d.x + v.y * d.y + v.z * d.z + v.w * d.w;
    }
#pragma unroll
    for (int o = 16; o; o >>= 1) {
        sc += __shfl_xor_sync(0xffffffffu, sc, o);
        sw += __shfl_xor_sync(0xffffffffu, sw, o);
        so += __shfl_xor_sync(0xffffffffu, so, o);
    }
    if (lane == 0) {
        float mask = (sal[row] >= 0.f) ? 1.f : 0.f;
        float z = sc + bc[0];
        g_center_pred[row] = (1.f / (1.f + expf(-z))) * mask;
        g_window_pred[row] = sw + bw[0];
        g_offset_pred[row] = so + bo[0];
    }
}

// bitonic compare-exchange via warp shuffle (j <= 16); i = element index, k = block size
__device__ __forceinline__ u64 bshfl(u64 v, int i, int j, int k) {
    u64 pv = __shfl_xor_sync(0xffffffffu, v, j);
    bool lower = ((i & j) == 0);
    bool up = ((i & k) == 0);
    u64 mx = v > pv ? v : pv;
    u64 mn = v > pv ? pv : v;
    return (lower == up) ? mx : mn;
}

// in-thread compare-exchange; a at lower index; up => larger to lower index (descending)
__device__ __forceinline__ void cxpair(u64& a, u64& b, bool up) {
    u64 mx = a > b ? a : b;
    u64 mn = a > b ? b : a;
    a = up ? mx : mn;
    b = up ? mn : mx;
}

#define SORT_BAR() asm volatile("bar.sync 1, 512;" ::: "memory")

// ---------- fused targets+loss + NMS + bitonic-top-k + decode + finalize ----------
// One block (1024 thr) per batch row.
// Warps 0..15:  peak keys + register-resident bitonic top-128 (named barrier 1)
// Warps 16..31: targets + loss (concurrent, no barrier-1 usage)
__global__ void fused_tail_kernel(const float* __restrict__ boundary,
                                  const float* __restrict__ sal,
                                  float* __restrict__ out) {
    __shared__ float s_cp[TT];
    __shared__ u64   s_key[16 * 128];
    __shared__ int   s_valid[MM];
    __shared__ int   s_ci[MM];
    __shared__ int   s_rad[MM];
    __shared__ float s_inv[MM];
    __shared__ float s_win[MM];
    __shared__ float s_cfrac[MM];
    __shared__ int   s_last;

    int b = blockIdx.x, tid = threadIdx.x;
    int w = tid >> 5, lane = tid & 31;

    // object params (loaded by loss-side warp 16 so loss warps own the data path)
    if (tid >= 512 && tid < 512 + MM) {
        int m = tid - 512;
        float b0 = boundary[(b * MM + m) * 2 + 0];
        float b1 = boundary[(b * MM + m) * 2 + 1];
        int valid = (b0 != -1.0f);
        float b0c = b0 * 0.5f;
        float b1c = (b1 - 2.0f) * 0.5f;
        float center = fminf((b0c + b1c) * 0.5f, (float)TT - 0.5f);
        float window = b1c - b0c;
        int radius = (int)(window * 0.2f);
        float sigma = ((float)radius + 1.0f) * 0.2f;
        int ci = (int)center;
        s_valid[m] = valid;
        s_ci[m]    = ci;
        s_rad[m]   = radius;
        s_inv[m]   = 1.0f / (2.0f * sigma * sigma);
        s_win[m]   = window;
        s_cfrac[m] = center - (float)ci;
    }
    // load cp row into smem (all threads)
    for (int t = tid; t < TT; t += 1024) s_cp[t] = g_center_pred[b * TT + t];
    __syncthreads();

    if (w >= 16) {
        // ================= LOSS WARPS =================
        int ltid = tid - 512;   // 0..511
        float cs = 0.f, ws = 0.f, os = 0.f;
#pragma unroll
        for (int c = 0; c < 4; c++) {
            int t = ltid + 512 * c;
            float ct = 0.f;
            int last = -1;
#pragma unroll
            for (int j = 0; j < MM; j++) {
                if (!s_valid[j]) continue;
                int d = t - s_ci[j];
                if (abs(d) <= s_rad[j]) ct = fmaxf(ct, expf(-(float)(d * d) * s_inv[j]));
                if (d == 0) last = j;
            }
            int idx = b * TT + t;
            float mask = (sal[idx] >= 0.f) ? 1.f : 0.f;
            float cp = s_cp[t];
            float pos = (ct == 1.0f) ? 1.f : 0.f;
            float omc = 1.f - cp;
            float pl = -logf(cp + 1e-12f) * omc * omc * pos;
            float omt = 1.f - ct;
            float o2 = omt * omt;
            float nl = -logf(omc + 1e-12f) * cp * cp * (o2 * o2);
            cs += (pl + nl) * mask;
            if (last >= 0) {
                ws += fabsf(g_window_pred[idx] - s_win[last]);
                os += fabsf(g_offset_pred[idx] - s_cfrac[last]);
            }
        }
#pragma unroll
        for (int o = 16; o; o >>= 1) {
            cs += __shfl_xor_sync(0xffffffffu, cs, o);
            ws += __shfl_xor_sync(0xffffffffu, ws, o);
            os += __shfl_xor_sync(0xffffffffu, os, o);
        }
        if (lane == 0) {
            atomicAdd(&g_acc[0], cs);
            atomicAdd(&g_acc[1], ws);
            atomicAdd(&g_acc[2], os);
        }
        if (tid == 512) {
            int cnt = 0;
#pragma unroll
            for (int j = 0; j < MM; j++) cnt += s_valid[j];
            atomicAdd(&g_acc[3], (float)cnt);
        }
    } else {
        // ================= SORT WARPS =================
        // keys: (f32bits(cpv) << 32) | (T-1-t): desc sort => value desc, index asc
        u64 v[4];
#pragma unroll
        for (int r = 0; r < 4; r++) {
            int i = r * 32 + lane;
            int t = w * 128 + i;
            float c = s_cp[t];
            float l = (t > 0)      ? s_cp[t - 1] : -INFINITY;
            float rr = (t < TT - 1) ? s_cp[t + 1] : -INFINITY;
            float hmax = fmaxf(c, fmaxf(l, rr));
            float cpv = (hmax == c) ? c : 0.f;
            v[r] = ((u64)__float_as_uint(cpv) << 32) | (unsigned int)(TT - 1 - t);
        }

        // full descending bitonic sort of this warp's 128-element segment (registers only)
#pragma unroll
        for (int k = 2; k <= 128; k <<= 1) {
#pragma unroll
            for (int j = 64; j > 0; j >>= 1) {
                if (j >= k) continue;
                if (j >= 32) {
                    int s = j >> 5;  // 1 or 2
#pragma unroll
                    for (int r = 0; r < 4; r++) {
                        if ((r & s) == 0) {
                            int iL = r * 32 + lane;
                            cxpair(v[r], v[r | s], (iL & k) == 0);
                        }
                    }
                } else {
#pragma unroll
                    for (int r = 0; r < 4; r++) v[r] = bshfl(v[r], r * 32 + lane, j, k);
                }
            }
        }

        // 4 max-merge levels: 16 runs -> 1 run of the exact top-128
        for (int m = 0; m < 4; m++) {
            int h = 1 << m;
            bool valid = (w & (h - 1)) == 0;
            if (valid) {
#pragma unroll
                for (int r = 0; r < 4; r++) s_key[w * 128 + r * 32 + lane] = v[r];
            }
            SORT_BAR();
            if ((w & (2 * h - 1)) == 0) {
                int p = w + h;
#pragma unroll
                for (int r = 0; r < 4; r++) {
                    int i = r * 32 + lane;
                    u64 bv = s_key[p * 128 + 127 - i];
                    v[r] = v[r] > bv ? v[r] : bv;      // C[i] = max(A[i], B[127-i])
                }
                // bitonic merge of 128 (descending)
                cxpair(v[0], v[2], true);
                cxpair(v[1], v[3], true);
                cxpair(v[0], v[1], true);
                cxpair(v[2], v[3], true);
#pragma unroll
                for (int j = 16; j > 0; j >>= 1) {
#pragma unroll
                    for (int r = 0; r < 4; r++) v[r] = bshfl(v[r], r * 32 + lane, j, 256);
                }
            }
        }
        if (w == 0) {
#pragma unroll
            for (int r = 0; r < 4; r++) s_key[r * 32 + lane] = v[r];
        }
        SORT_BAR();

        // decode top-100 (threads 0..99 are in sorter warps)
        if (tid < TOPK_N) {
            u64 key = s_key[tid];
            float score = __uint_as_float((unsigned int)(key >> 32));
            int idx = TT - 1 - (int)(key & 0xffffffffu);
            float off = fmaxf(g_offset_pred[b * TT + idx], 0.f);
            float center = (float)idx + off;
            float window = fmaxf(g_window_pred[b * TT + idx], 0.f);
            float lo = fminf(fmaxf(center - window * 0.5f, 0.f), (float)(TT - 1)) * 2.0f;
            float hi = fminf(fmaxf(center + window * 0.5f, 0.f), (float)(TT - 1)) * 2.0f + 2.0f;
            float* o = out + ((size_t)b * TOPK_N + tid) * 3;
            o[0] = lo; o[1] = hi; o[2] = score;
        }
    }

    // ---- finalize: last block writes losses ----
    __syncthreads();
    if (tid == 0) {
        __threadfence();
        unsigned int old = atomicAdd(&g_ticket, 1u);
        s_last = (old == BB - 1) ? 1 : 0;
    }
    __syncthreads();
    if (s_last && tid == 0) {
        __threadfence();
        float avg = g_acc[3];
        out[BB * TOPK_N * 3 + 0] = g_acc[0] / avg;
        out[BB * TOPK_N * 3 + 1] = 0.1f * g_acc[1] / avg;
        out[BB * TOPK_N * 3 + 2] = g_acc[2] / avg;
        g_ticket = 0;   // reset for next graph replay
    }
}

extern "C" void kernel_launch(void* const* d_in, const int* in_sizes, int n_in,
                              void* d_out, int out_size) {
    const float* x        = (const float*)d_in[0];
    const float* w_center = (const float*)d_in[1];
    const float* b_center = (const float*)d_in[2];
    const float* w_window = (const float*)d_in[3];
    const float* b_window = (const float*)d_in[4];
    const float* w_offset = (const float*)d_in[5];
    const float* b_offset = (const float*)d_in[6];
    const float* saliency = (const float*)d_in[7];
    const float* boundary = (const float*)d_in[8];
    float* out = (float*)d_out;

    proj_kernel<<<(BB * TT) / 8, 256>>>(x, w_center, b_center, w_window, b_window,
                                        w_offset, b_offset, saliency);
    fused_tail_kernel<<<BB, 1024>>>(boundary, saliency, out);
}